// round 7
// baseline (speedup 1.0000x reference)
#include <cuda_runtime.h>
#include <cuda_fp16.h>
#include <cstdint>
#include <math.h>

#define BATCH 8192
#define INDIM 1024
#define HID   2048
#define KTOT  3072
#define NTOT  8192

#define BM 128
#define BN 128
#define BK 64
#define STAGES 4
#define THREADS 256
#define STAGE_BYTES (BM * BK * 2 + BN * BK * 2)
#define SMEM_BYTES (STAGES * STAGE_BYTES)

__device__ __half g_xh [(size_t)BATCH * KTOT];
__device__ __half g_wt [(size_t)NTOT  * KTOT];
__device__ __half g_wrt[(size_t)HID   * INDIM];
__device__ float  g_gates[(size_t)BATCH * NTOT];
__device__ float  g_xres [(size_t)BATCH * HID];

__device__ __forceinline__ uint32_t smem_u32(const void* p) {
    uint32_t a;
    asm("{ .reg .u64 t; cvta.to.shared.u64 t, %1; cvt.u32.u64 %0, t; }" : "=r"(a) : "l"(p));
    return a;
}
__device__ __forceinline__ uint32_t swz(uint32_t o) { return o ^ ((o >> 3) & 0x70); }
__device__ __forceinline__ void cp16(uint32_t dst, const void* src) {
    asm volatile("cp.async.cg.shared.global [%0], [%1], 16;" :: "r"(dst), "l"(src));
}
#define CP_COMMIT() asm volatile("cp.async.commit_group;" ::: "memory")
#define CP_WAIT(n)  asm volatile("cp.async.wait_group %0;" :: "n"(n) : "memory")

__device__ __forceinline__ void ldsm_x4(uint32_t* d, uint32_t addr) {
    asm volatile("ldmatrix.sync.aligned.m8n8.x4.shared.b16 {%0,%1,%2,%3}, [%4];"
        : "=r"(d[0]), "=r"(d[1]), "=r"(d[2]), "=r"(d[3]) : "r"(addr));
}
__device__ __forceinline__ void mma16816(float* c, const uint32_t* a, const uint32_t* b) {
    asm volatile(
        "mma.sync.aligned.m16n8k16.row.col.f32.f16.f16.f32 "
        "{%0,%1,%2,%3}, {%4,%5,%6,%7}, {%8,%9}, {%0,%1,%2,%3};"
        : "+f"(c[0]), "+f"(c[1]), "+f"(c[2]), "+f"(c[3])
        : "r"(a[0]), "r"(a[1]), "r"(a[2]), "r"(a[3]), "r"(b[0]), "r"(b[1]));
}

__global__ void prep_xh(const float* __restrict__ x, const float* __restrict__ h) {
    int k = blockIdx.x * 256 + threadIdx.x;
    int b = blockIdx.y;
    float v = (k < INDIM) ? x[(size_t)b * INDIM + k]
                          : h[(size_t)b * HID + (k - INDIM)];
    g_xh[(size_t)b * KTOT + k] = __float2half_rn(v);
}

__global__ void prep_wg(const float* __restrict__ Wg) {
    __shared__ float t[32][33];
    int k0 = blockIdx.x * 32, h0 = blockIdx.y * 32, g = blockIdx.z;
    const float* src = Wg + ((size_t)g * KTOT + k0) * HID + h0;
#pragma unroll
    for (int i = 0; i < 4; i++)
        t[threadIdx.y + 8 * i][threadIdx.x] = src[(size_t)(threadIdx.y + 8 * i) * HID + threadIdx.x];
    __syncthreads();
#pragma unroll
    for (int i = 0; i < 4; i++) {
        int hh = threadIdx.y + 8 * i;
        g_wt[((size_t)(g * HID + h0 + hh)) * KTOT + k0 + threadIdx.x] =
            __float2half_rn(t[threadIdx.x][hh]);
    }
}

__global__ void prep_wr(const float* __restrict__ Wr) {
    __shared__ float t[32][33];
    int k0 = blockIdx.x * 32, h0 = blockIdx.y * 32;
    const float* src = Wr + (size_t)k0 * HID + h0;
#pragma unroll
    for (int i = 0; i < 4; i++)
        t[threadIdx.y + 8 * i][threadIdx.x] = src[(size_t)(threadIdx.y + 8 * i) * HID + threadIdx.x];
    __syncthreads();
#pragma unroll
    for (int i = 0; i < 4; i++) {
        int hh = threadIdx.y + 8 * i;
        g_wrt[((size_t)(h0 + hh)) * INDIM + k0 + threadIdx.x] =
            __float2half_rn(t[threadIdx.x][hh]);
    }
}

__device__ __forceinline__ void load_stage(uint32_t sA, uint32_t sB,
                                           const __half* __restrict__ A,
                                           const __half* __restrict__ Bw,
                                           int m0, int n0, int k0,
                                           int lda, int ldb, int tid) {
#pragma unroll
    for (int it = 0; it < 4; it++) {
        int i = tid + it * THREADS;
        int r = i >> 3, cgr = i & 7;
        uint32_t sw = swz((uint32_t)(r * 128 + cgr * 16));
        cp16(sA + sw, A  + (size_t)(m0 + r) * lda + k0 + cgr * 8);
        cp16(sB + sw, Bw + (size_t)(n0 + r) * ldb + k0 + cgr * 8);
    }
}

__global__ void __launch_bounds__(THREADS, 1)
gemm_nt(const __half* __restrict__ A, const __half* __restrict__ Bw,
        float* __restrict__ C, int K, int lda, int ldC) {
    extern __shared__ char smem[];
    uint32_t sb = smem_u32(smem);
    const int tid = threadIdx.x, lane = tid & 31, wid = tid >> 5;
    const int wm = wid & 3;
    const int wn = wid >> 2;
    const int m0 = blockIdx.x * BM;
    const int n0 = blockIdx.y * BN;
    const int nch = K / BK;

    float acc[2][8][4];
#pragma unroll
    for (int mi = 0; mi < 2; mi++)
#pragma unroll
        for (int ni = 0; ni < 8; ni++)
#pragma unroll
            for (int e = 0; e < 4; e++) acc[mi][ni][e] = 0.0f;

#pragma unroll
    for (int s = 0; s < STAGES - 1; s++) {
        load_stage(sb + s * STAGE_BYTES, sb + s * STAGE_BYTES + BM * BK * 2,
                   A, Bw, m0, n0, s * BK, lda, K, tid);
        CP_COMMIT();
    }

    for (int c = 0; c < nch; c++) {
        CP_WAIT(STAGES - 2);
        __syncthreads();

        int cl = c + STAGES - 1;
        if (cl < nch) {
            int s = cl % STAGES;
            load_stage(sb + s * STAGE_BYTES, sb + s * STAGE_BYTES + BM * BK * 2,
                       A, Bw, m0, n0, cl * BK, lda, K, tid);
        }
        CP_COMMIT();

        uint32_t sA = sb + (c % STAGES) * STAGE_BYTES;
        uint32_t sB = sA + BM * BK * 2;

#pragma unroll
        for (int ks = 0; ks < 4; ks++) {
            uint32_t af[2][4];
            {
                int ra = lane & 15;
                int kg = ks * 2 + (lane >> 4);
#pragma unroll
                for (int mi = 0; mi < 2; mi++) {
                    uint32_t off = (uint32_t)((wm * 32 + mi * 16 + ra) * 128 + kg * 16);
                    ldsm_x4(af[mi], sA + swz(off));
                }
            }
            uint32_t bf[8][2];
            {
                int rb = (lane & 7) + ((lane >> 4) << 3);
                int kg = ks * 2 + ((lane >> 3) & 1);
#pragma unroll
                for (int nq = 0; nq < 4; nq++) {
                    uint32_t t[4];
                    uint32_t off = (uint32_t)((wn * 64 + nq * 16 + rb) * 128 + kg * 16);
                    ldsm_x4(t, sB + swz(off));
                    bf[nq * 2][0] = t[0]; bf[nq * 2][1] = t[1];
                    bf[nq * 2 + 1][0] = t[2]; bf[nq * 2 + 1][1] = t[3];
                }
            }
#pragma unroll
            for (int mi = 0; mi < 2; mi++)
#pragma unroll
                for (int ni = 0; ni < 8; ni++)
                    mma16816(acc[mi][ni], af[mi], bf[ni]);
        }
    }

    const int gid = lane >> 2, tq = lane & 3;
#pragma unroll
    for (int mi = 0; mi < 2; mi++) {
#pragma unroll
        for (int ni = 0; ni < 8; ni++) {
            int m = m0 + wm * 32 + mi * 16 + gid;
            int n = n0 + wn * 64 + ni * 8 + tq * 2;
            *(float2*)&C[(size_t)m * ldC + n]       = make_float2(acc[mi][ni][0], acc[mi][ni][1]);
            *(float2*)&C[(size_t)(m + 8) * ldC + n] = make_float2(acc[mi][ni][2], acc[mi][ni][3]);
        }
    }
}

__global__ void lstm_epilogue(const float* __restrict__ c_prev,
                              const float* __restrict__ bg,
                              const float* __restrict__ br,
                              float* __restrict__ out) {
    int hcol = blockIdx.x * 256 + threadIdx.x;
    int b = blockIdx.y;
    const float* grow = g_gates + (size_t)b * NTOT;

    float pi = grow[hcol]           + bg[hcol];
    float pf = grow[HID + hcol]     + bg[HID + hcol];
    float po = grow[2 * HID + hcol] + bg[2 * HID + hcol];
    float pc = grow[3 * HID + hcol] + bg[3 * HID + hcol];

    float iv = 1.0f / (1.0f + __expf(-pi));
    float fv = 1.0f / (1.0f + __expf(-pf));
    float ov = 1.0f / (1.0f + __expf(-po));
    float ch = tanhf(pc);

    float ct = fv * c_prev[(size_t)b * HID + hcol] + iv * ch;
    float xr = g_xres[(size_t)b * HID + hcol] + br[hcol];
    float ht = ov * tanhf(ct) + xr;

    out[(size_t)b * HID + hcol] = ht;
    out[(size_t)BATCH * HID + (size_t)b * HID + hcol] = ct;
}

extern "C" void kernel_launch(void* const* d_in, const int* in_sizes, int n_in,
                              void* d_out, int out_size) {
    const float* x  = (const float*)d_in[0];
    const float* h  = (const float*)d_in[1];
    const float* c  = (const float*)d_in[2];
    const float* Wg = (const float*)d_in[3];
    const float* bg = (const float*)d_in[4];
    const float* Wr = (const float*)d_in[5];
    const float* br = (const float*)d_in[6];
    float* out = (float*)d_out;

    prep_xh<<<dim3(KTOT / 256, BATCH), 256>>>(x, h);
    prep_wg<<<dim3(KTOT / 32, HID / 32, 4), dim3(32, 8)>>>(Wg);
    prep_wr<<<dim3(INDIM / 32, HID / 32), dim3(32, 8)>>>(Wr);

    cudaFuncSetAttribute(gemm_nt, cudaFuncAttributeMaxDynamicSharedMemorySize, SMEM_BYTES);

    __half* xh;  cudaGetSymbolAddress((void**)&xh,  g_xh);
    __half* wt;  cudaGetSymbolAddress((void**)&wt,  g_wt);
    __half* wrt; cudaGetSymbolAddress((void**)&wrt, g_wrt);
    float* gts;  cudaGetSymbolAddress((void**)&gts, g_gates);
    float* xrs;  cudaGetSymbolAddress((void**)&xrs, g_xres);

    // gates: A stride KTOT, B = g_wt (rows of length KTOT)
    gemm_nt<<<dim3(BATCH / BM, NTOT / BN), THREADS, SMEM_BYTES>>>(xh, wt, gts, KTOT, KTOT, NTOT);
    // residual: K = INDIM but A rows still stride KTOT (first 1024 cols of g_xh are x_t)
    gemm_nt<<<dim3(BATCH / BM, HID / BN), THREADS, SMEM_BYTES>>>(xh, wrt, xrs, INDIM, KTOT, HID);

    lstm_epilogue<<<dim3(HID / 256, BATCH), 256>>>(c, bg, br, out);

    (void)in_sizes; (void)n_in; (void)out_size;
}

// round 8
// speedup vs baseline: 1.1073x; 1.1073x over previous
#include <cuda_runtime.h>
#include <cuda_fp16.h>
#include <cstdint>
#include <math.h>

#define BATCH 8192
#define INDIM 1024
#define HID   2048
#define KTOT  3072
#define NTOT  8192

#define BM 128
#define BN 256
#define BK 64
#define STAGES 3
#define THREADS 256
#define A_BYTES (BM * BK * 2)               // 16384
#define B_BYTES (BN * BK * 2)               // 32768
#define STAGE_BYTES (A_BYTES + B_BYTES)     // 49152
#define SMEM_BYTES (STAGES * STAGE_BYTES)   // 147456

__device__ __half g_xh [(size_t)BATCH * KTOT];
__device__ __half g_wt [(size_t)NTOT  * KTOT];
__device__ __half g_wrt[(size_t)HID   * INDIM];
__device__ float  g_gates[(size_t)BATCH * NTOT];
__device__ float  g_xres [(size_t)BATCH * HID];

__device__ __forceinline__ uint32_t smem_u32(const void* p) {
    uint32_t a;
    asm("{ .reg .u64 t; cvta.to.shared.u64 t, %1; cvt.u32.u64 %0, t; }" : "=r"(a) : "l"(p));
    return a;
}
__device__ __forceinline__ uint32_t swz(uint32_t o) { return o ^ ((o >> 3) & 0x70); }
__device__ __forceinline__ void cp16(uint32_t dst, const void* src) {
    asm volatile("cp.async.cg.shared.global [%0], [%1], 16;" :: "r"(dst), "l"(src));
}
#define CP_COMMIT() asm volatile("cp.async.commit_group;" ::: "memory")
#define CP_WAIT(n)  asm volatile("cp.async.wait_group %0;" :: "n"(n) : "memory")

__device__ __forceinline__ void ldsm_x4(uint32_t* d, uint32_t addr) {
    asm volatile("ldmatrix.sync.aligned.m8n8.x4.shared.b16 {%0,%1,%2,%3}, [%4];"
        : "=r"(d[0]), "=r"(d[1]), "=r"(d[2]), "=r"(d[3]) : "r"(addr));
}
__device__ __forceinline__ void mma16816(float* c, const uint32_t* a, const uint32_t* b) {
    asm volatile(
        "mma.sync.aligned.m16n8k16.row.col.f32.f16.f16.f32 "
        "{%0,%1,%2,%3}, {%4,%5,%6,%7}, {%8,%9}, {%0,%1,%2,%3};"
        : "+f"(c[0]), "+f"(c[1]), "+f"(c[2]), "+f"(c[3])
        : "r"(a[0]), "r"(a[1]), "r"(a[2]), "r"(a[3]), "r"(b[0]), "r"(b[1]));
}

// ---------------- pre-passes ----------------
__global__ void prep_xh(const float* __restrict__ x, const float* __restrict__ h) {
    int k = blockIdx.x * 256 + threadIdx.x;
    int b = blockIdx.y;
    float v = (k < INDIM) ? x[(size_t)b * INDIM + k]
                          : h[(size_t)b * HID + (k - INDIM)];
    g_xh[(size_t)b * KTOT + k] = __float2half_rn(v);
}

__global__ void prep_wg(const float* __restrict__ Wg) {
    __shared__ float t[32][33];
    int k0 = blockIdx.x * 32, h0 = blockIdx.y * 32, g = blockIdx.z;
    const float* src = Wg + ((size_t)g * KTOT + k0) * HID + h0;
#pragma unroll
    for (int i = 0; i < 4; i++)
        t[threadIdx.y + 8 * i][threadIdx.x] = src[(size_t)(threadIdx.y + 8 * i) * HID + threadIdx.x];
    __syncthreads();
#pragma unroll
    for (int i = 0; i < 4; i++) {
        int hh = threadIdx.y + 8 * i;
        g_wt[((size_t)(g * HID + h0 + hh)) * KTOT + k0 + threadIdx.x] =
            __float2half_rn(t[threadIdx.x][hh]);
    }
}

__global__ void prep_wr(const float* __restrict__ Wr) {
    __shared__ float t[32][33];
    int k0 = blockIdx.x * 32, h0 = blockIdx.y * 32;
    const float* src = Wr + (size_t)k0 * HID + h0;
#pragma unroll
    for (int i = 0; i < 4; i++)
        t[threadIdx.y + 8 * i][threadIdx.x] = src[(size_t)(threadIdx.y + 8 * i) * HID + threadIdx.x];
    __syncthreads();
#pragma unroll
    for (int i = 0; i < 4; i++) {
        int hh = threadIdx.y + 8 * i;
        g_wrt[((size_t)(h0 + hh)) * INDIM + k0 + threadIdx.x] =
            __float2half_rn(t[threadIdx.x][hh]);
    }
}

// ---------------- GEMM: C[m][n] = sum_k A[m][k] * Bw[n][k] ----------------
__device__ __forceinline__ void load_stage(uint32_t sA, uint32_t sB,
                                           const __half* __restrict__ A,
                                           const __half* __restrict__ Bw,
                                           int m0, int n0, int k0,
                                           int lda, int ldb, int tid) {
#pragma unroll
    for (int it = 0; it < 4; it++) {             // A: 128 rows x 8 x 16B
        int i = tid + it * THREADS;
        int r = i >> 3, cg = i & 7;
        uint32_t sw = swz((uint32_t)(r * 128 + cg * 16));
        cp16(sA + sw, A + (size_t)(m0 + r) * lda + k0 + cg * 8);
    }
#pragma unroll
    for (int it = 0; it < 8; it++) {             // B: 256 rows x 8 x 16B
        int i = tid + it * THREADS;
        int r = i >> 3, cg = i & 7;
        uint32_t sw = swz((uint32_t)(r * 128 + cg * 16));
        cp16(sB + sw, Bw + (size_t)(n0 + r) * ldb + k0 + cg * 8);
    }
}

__global__ void __launch_bounds__(THREADS, 1)
gemm_nt(const __half* __restrict__ A, const __half* __restrict__ Bw,
        float* __restrict__ C, int K, int lda, int ldC) {
    extern __shared__ char smem[];
    uint32_t sb = smem_u32(smem);
    const int tid = threadIdx.x, lane = tid & 31, wid = tid >> 5;
    const int wm = wid & 1;                 // 2 warps along M (64 rows each)
    const int wn = wid >> 1;                // 4 warps along N (64 cols each)
    const int m0 = blockIdx.x * BM;
    const int n0 = blockIdx.y * BN;
    const int nch = K / BK;

    float acc[4][8][4];
#pragma unroll
    for (int mi = 0; mi < 4; mi++)
#pragma unroll
        for (int ni = 0; ni < 8; ni++)
#pragma unroll
            for (int e = 0; e < 4; e++) acc[mi][ni][e] = 0.0f;

#pragma unroll
    for (int s = 0; s < STAGES - 1; s++) {
        load_stage(sb + s * STAGE_BYTES, sb + s * STAGE_BYTES + A_BYTES,
                   A, Bw, m0, n0, s * BK, lda, K, tid);
        CP_COMMIT();
    }

    for (int c = 0; c < nch; c++) {
        CP_WAIT(STAGES - 2);
        __syncthreads();

        int cl = c + STAGES - 1;
        if (cl < nch) {
            int s = cl % STAGES;
            load_stage(sb + s * STAGE_BYTES, sb + s * STAGE_BYTES + A_BYTES,
                       A, Bw, m0, n0, cl * BK, lda, K, tid);
        }
        CP_COMMIT();

        uint32_t sA = sb + (c % STAGES) * STAGE_BYTES;
        uint32_t sB = sA + A_BYTES;

#pragma unroll
        for (int ks = 0; ks < 4; ks++) {
            uint32_t af[4][4];
            {
                int ra = lane & 15;
                int kg = ks * 2 + (lane >> 4);
#pragma unroll
                for (int mi = 0; mi < 4; mi++) {
                    uint32_t off = (uint32_t)((wm * 64 + mi * 16 + ra) * 128 + kg * 16);
                    ldsm_x4(af[mi], sA + swz(off));
                }
            }
            uint32_t bf[8][2];
            {
                int rb = (lane & 7) + ((lane >> 4) << 3);
                int kg = ks * 2 + ((lane >> 3) & 1);
#pragma unroll
                for (int nq = 0; nq < 4; nq++) {
                    uint32_t t[4];
                    uint32_t off = (uint32_t)((wn * 64 + nq * 16 + rb) * 128 + kg * 16);
                    ldsm_x4(t, sB + swz(off));
                    bf[nq * 2][0] = t[0]; bf[nq * 2][1] = t[1];
                    bf[nq * 2 + 1][0] = t[2]; bf[nq * 2 + 1][1] = t[3];
                }
            }
#pragma unroll
            for (int mi = 0; mi < 4; mi++)
#pragma unroll
                for (int ni = 0; ni < 8; ni++)
                    mma16816(acc[mi][ni], af[mi], bf[ni]);
        }
    }

    const int gid = lane >> 2, tq = lane & 3;
#pragma unroll
    for (int mi = 0; mi < 4; mi++) {
#pragma unroll
        for (int ni = 0; ni < 8; ni++) {
            int m = m0 + wm * 64 + mi * 16 + gid;
            int n = n0 + wn * 64 + ni * 8 + tq * 2;
            *(float2*)&C[(size_t)m * ldC + n]       = make_float2(acc[mi][ni][0], acc[mi][ni][1]);
            *(float2*)&C[(size_t)(m + 8) * ldC + n] = make_float2(acc[mi][ni][2], acc[mi][ni][3]);
        }
    }
}

// ---------------- elementwise LSTM epilogue ----------------
__global__ void lstm_epilogue(const float* __restrict__ c_prev,
                              const float* __restrict__ bg,
                              const float* __restrict__ br,
                              float* __restrict__ out) {
    int hcol = blockIdx.x * 256 + threadIdx.x;
    int b = blockIdx.y;
    const float* grow = g_gates + (size_t)b * NTOT;

    float pi = grow[hcol]           + bg[hcol];
    float pf = grow[HID + hcol]     + bg[HID + hcol];
    float po = grow[2 * HID + hcol] + bg[2 * HID + hcol];
    float pc = grow[3 * HID + hcol] + bg[3 * HID + hcol];

    float iv = 1.0f / (1.0f + __expf(-pi));
    float fv = 1.0f / (1.0f + __expf(-pf));
    float ov = 1.0f / (1.0f + __expf(-po));
    float ch = tanhf(pc);

    float ct = fv * c_prev[(size_t)b * HID + hcol] + iv * ch;
    float xr = g_xres[(size_t)b * HID + hcol] + br[hcol];
    float ht = ov * tanhf(ct) + xr;

    out[(size_t)b * HID + hcol] = ht;
    out[(size_t)BATCH * HID + (size_t)b * HID + hcol] = ct;
}

extern "C" void kernel_launch(void* const* d_in, const int* in_sizes, int n_in,
                              void* d_out, int out_size) {
    const float* x  = (const float*)d_in[0];
    const float* h  = (const float*)d_in[1];
    const float* c  = (const float*)d_in[2];
    const float* Wg = (const float*)d_in[3];
    const float* bg = (const float*)d_in[4];
    const float* Wr = (const float*)d_in[5];
    const float* br = (const float*)d_in[6];
    float* out = (float*)d_out;

    prep_xh<<<dim3(KTOT / 256, BATCH), 256>>>(x, h);
    prep_wg<<<dim3(KTOT / 32, HID / 32, 4), dim3(32, 8)>>>(Wg);
    prep_wr<<<dim3(INDIM / 32, HID / 32), dim3(32, 8)>>>(Wr);

    cudaFuncSetAttribute(gemm_nt, cudaFuncAttributeMaxDynamicSharedMemorySize, SMEM_BYTES);

    __half* xh;  cudaGetSymbolAddress((void**)&xh,  g_xh);
    __half* wt;  cudaGetSymbolAddress((void**)&wt,  g_wt);
    __half* wrt; cudaGetSymbolAddress((void**)&wrt, g_wrt);
    float* gts;  cudaGetSymbolAddress((void**)&gts, g_gates);
    float* xrs;  cudaGetSymbolAddress((void**)&xrs, g_xres);

    // gates: [8192 x 3072] x [8192 x 3072]^T -> [8192 x 8192]
    gemm_nt<<<dim3(BATCH / BM, NTOT / BN), THREADS, SMEM_BYTES>>>(xh, wt, gts, KTOT, KTOT, NTOT);
    // residual: K = INDIM, A rows stride KTOT (first 1024 cols of g_xh are x_t)
    gemm_nt<<<dim3(BATCH / BM, HID / BN), THREADS, SMEM_BYTES>>>(xh, wrt, xrs, INDIM, KTOT, HID);

    lstm_epilogue<<<dim3(HID / 256, BATCH), 256>>>(c, bg, br, out);

    (void)in_sizes; (void)n_in; (void)out_size;
}